// round 1
// baseline (speedup 1.0000x reference)
#include <cuda_runtime.h>

// ---------------------------------------------------------------------------
// Problem-size bounds (inputs are fixed-shape: N=400000 verts, F=2000000 tets)
// ---------------------------------------------------------------------------
#define MAXN 400000
#define MAXF 2000000
#define MAXSLOT (6 * MAXF)            // max crossing-edge slots
#define MAXVAL (MAXN + MAXSLOT)       // value domain of all_tets entries
#define MAXT (3 * MAXF)               // max tetmesh tets
#define TPB 256
#define GRID(n) (((n) + TPB - 1) / TPB)

// ---------------------------------------------------------------------------
// Marching-tetrahedra tables (static init -> baked into cubin, no memcpy)
// ---------------------------------------------------------------------------
__constant__ int c_tri[16][6] = {
    {-1,-1,-1,-1,-1,-1},{1,0,2,-1,-1,-1},{4,0,3,-1,-1,-1},{1,4,2,1,3,4},
    {3,1,5,-1,-1,-1},{2,3,0,2,5,3},{1,4,0,1,5,4},{4,2,5,-1,-1,-1},
    {4,5,2,-1,-1,-1},{4,1,0,4,5,1},{3,2,0,3,5,2},{1,3,5,-1,-1,-1},
    {4,1,2,4,3,1},{3,0,4,-1,-1,-1},{2,0,1,-1,-1,-1},{-1,-1,-1,-1,-1,-1}};
__constant__ int c_ntri[16] = {0,1,1,2,1,2,2,1,1,2,2,1,2,1,1,0};
__constant__ int c_ntet[16] = {0,1,1,3,1,3,3,3,1,3,3,3,3,3,3,1};
__constant__ int c_tet[16][12] = {
    {-1,-1,-1,-1,-1,-1,-1,-1,-1,-1,-1,-1},{0,4,5,6,-1,-1,-1,-1,-1,-1,-1,-1},
    {1,4,8,7,-1,-1,-1,-1,-1,-1,-1,-1},{7,1,8,6,5,1,7,6,5,0,1,6},
    {2,5,7,9,-1,-1,-1,-1,-1,-1,-1,-1},{4,0,6,7,9,0,7,6,7,0,9,2},
    {4,1,9,8,5,1,9,4,5,1,2,9},{6,0,1,2,8,6,1,2,9,6,8,2},
    {3,6,9,8,-1,-1,-1,-1,-1,-1,-1,-1},{5,0,4,8,5,0,8,3,5,8,9,3},
    {1,4,7,3,4,7,6,3,9,6,7,3},{0,1,5,3,5,1,9,3,5,1,7,9},
    {5,2,3,7,3,6,5,8,3,5,7,8},{0,4,7,8,0,3,8,7,0,3,7,2},
    {4,1,2,3,4,3,2,5,4,3,5,6},{0,1,2,3,-1,-1,-1,-1,-1,-1,-1,-1}};
__constant__ int c_be[12] = {0,1, 0,2, 0,3, 1,2, 1,3, 2,3};

// ---------------------------------------------------------------------------
// Device scratch (static __device__ globals — allocation-free at runtime)
// ---------------------------------------------------------------------------
__device__ unsigned char      g_occ[MAXN];
__device__ unsigned char      g_ti[MAXF];
__device__ unsigned           g_sc[5 * MAXF];     // flags -> in-place exclusive scans
__device__ unsigned           g_bcnt[MAXN];
__device__ unsigned           g_boff[MAXN];
__device__ unsigned           g_bfill[MAXN];
__device__ unsigned           g_ucnt[MAXN];
__device__ unsigned           g_urank[MAXN];
__device__ unsigned long long g_keys[MAXSLOT];    // (b<<24)|slot per crossing slot
__device__ unsigned           g_aux[MAXSLOT];     // (localRank<<1)|head
__device__ int                g_idxmap[MAXSLOT];  // slot -> unique crossing edge rank
__device__ int                g_uea[MAXSLOT];     // unique edge endpoint a
__device__ int                g_ueb[MAXSLOT];     // unique edge endpoint b
__device__ float              g_verts[3 * MAXSLOT];
__device__ int                g_alltets[4 * MAXT];
__device__ unsigned           g_pres[MAXVAL];
__device__ unsigned           g_rank2[MAXVAL];
__device__ unsigned           g_part[16384];      // scan partials
__device__ unsigned           g_cnt[16];
// g_cnt: [0]=E [1]=NT1 [2]=NT2 [3]=T1 [4]=T3 [5]=INNER [6]=U [7]=nslots [8]=T

// ---------------------------------------------------------------------------
// Generic exclusive scan over registered device arrays (3-kernel, capture-safe)
// ---------------------------------------------------------------------------
__device__ __forceinline__ unsigned* scan_arr(int s) {
    switch (s) {
        case 0: return g_sc;
        case 1: return g_sc + MAXF;
        case 2: return g_sc + 2 * MAXF;
        case 3: return g_sc + 3 * MAXF;
        case 4: return g_sc + 4 * MAXF;
        case 5: return g_bcnt;
        case 6: return g_boff;
        case 7: return g_ucnt;
        case 8: return g_urank;
        case 9: return g_pres;
        default: return g_rank2;
    }
}

__global__ void scan_k1(int insel, int outsel, int n) {
    __shared__ unsigned sh[TPB];
    const unsigned* in = scan_arr(insel);
    unsigned* out = scan_arr(outsel);
    int t = threadIdx.x;
    int base = blockIdx.x * (TPB * 8) + t * 8;
    unsigned v[8]; unsigned s = 0;
#pragma unroll
    for (int i = 0; i < 8; i++) {
        unsigned x = (base + i < n) ? in[base + i] : 0u;
        v[i] = s; s += x;
    }
    sh[t] = s; __syncthreads();
    for (int d = 1; d < TPB; d <<= 1) {
        unsigned y = 0;
        if (t >= d) y = sh[t - d];
        __syncthreads();
        if (t >= d) sh[t] += y;
        __syncthreads();
    }
    unsigned off = (t > 0) ? sh[t - 1] : 0u;
    if (t == 0) g_part[blockIdx.x] = sh[TPB - 1];
    __syncthreads();
#pragma unroll
    for (int i = 0; i < 8; i++)
        if (base + i < n) out[base + i] = v[i] + off;
}

__global__ void scan_k2(int nb, int counterIdx) {
    __shared__ unsigned sh[1024];
    __shared__ unsigned carry_s;
    int t = threadIdx.x;
    if (t == 0) carry_s = 0;
    __syncthreads();
    for (int base = 0; base < nb; base += 1024) {
        int i = base + t;
        unsigned x = (i < nb) ? g_part[i] : 0u;
        sh[t] = x; __syncthreads();
        for (int d = 1; d < 1024; d <<= 1) {
            unsigned y = 0;
            if (t >= d) y = sh[t - d];
            __syncthreads();
            if (t >= d) sh[t] += y;
            __syncthreads();
        }
        unsigned c = carry_s;
        unsigned excl = c + ((t > 0) ? sh[t - 1] : 0u);
        unsigned tot = sh[1023];
        __syncthreads();
        if (i < nb) g_part[i] = excl;
        if (t == 0) carry_s = c + tot;
        __syncthreads();
    }
    if (t == 0 && counterIdx >= 0) g_cnt[counterIdx] = carry_s;
}

__global__ void scan_k3(int outsel, int n) {
    unsigned* out = scan_arr(outsel);
    unsigned add = g_part[blockIdx.x];
    int base = blockIdx.x * (TPB * 8) + threadIdx.x * 8;
#pragma unroll
    for (int i = 0; i < 8; i++)
        if (base + i < n) out[base + i] += add;
}

static void run_scan(int insel, int outsel, int n, int counterIdx) {
    int nb = (n + TPB * 8 - 1) / (TPB * 8);
    scan_k1<<<nb, TPB>>>(insel, outsel, n);
    scan_k2<<<1, 1024>>>(nb, counterIdx);
    scan_k3<<<nb, TPB>>>(outsel, n);
}

// ---------------------------------------------------------------------------
// Pipeline kernels
// ---------------------------------------------------------------------------
__global__ void k_clear_buckets(int n) {
    int i = blockIdx.x * blockDim.x + threadIdx.x;
    if (i < n) { g_bcnt[i] = 0; g_bfill[i] = 0; }
}

__global__ void k_clear_pres(int n) {
    int i = blockIdx.x * blockDim.x + threadIdx.x;
    if (i < n) g_pres[i] = 0;
}

__global__ void k_occ(const float* __restrict__ sdf, const float* __restrict__ th, int N) {
    int i = blockIdx.x * blockDim.x + threadIdx.x;
    if (i >= N) return;
    float t = *th;
    float s = sdf[i];
    g_occ[i] = (s > 0.0f && s <= t) ? 1 : 0;
}

// classify tets: ti byte, class-flag arrays, crossing-edge bucket histogram
__global__ void k_ti(const int* __restrict__ tet, int F) {
    int f = blockIdx.x * blockDim.x + threadIdx.x;
    if (f >= F) return;
    int v[4]; unsigned o[4];
#pragma unroll
    for (int j = 0; j < 4; j++) { v[j] = tet[4 * f + j]; o[j] = g_occ[v[j]]; }
    unsigned ti = o[0] | (o[1] << 1) | (o[2] << 2) | (o[3] << 3);
    g_ti[f] = (unsigned char)ti;
    bool valid = (ti >= 1u && ti <= 14u);
    int nt = c_ntri[ti], ntt = c_ntet[ti];
    g_sc[0 * MAXF + f] = (valid && nt == 1) ? 1u : 0u;
    g_sc[1 * MAXF + f] = (valid && nt == 2) ? 1u : 0u;
    g_sc[2 * MAXF + f] = (valid && ntt == 1) ? 1u : 0u;
    g_sc[3 * MAXF + f] = (valid && ntt == 3) ? 1u : 0u;
    g_sc[4 * MAXF + f] = (ti == 15u) ? 1u : 0u;
    if (valid) {
#pragma unroll
        for (int e = 0; e < 6; e++) {
            int p0 = c_be[2 * e], p1 = c_be[2 * e + 1];
            if (o[p0] != o[p1]) {
                int a = v[p0], b = v[p1];
                int amin = a < b ? a : b;
                atomicAdd(&g_bcnt[amin], 1u);
            }
        }
    }
}

__global__ void k_scatter(const int* __restrict__ tet, int F) {
    int f = blockIdx.x * blockDim.x + threadIdx.x;
    if (f >= F) return;
    unsigned ti = g_ti[f];
    if (ti < 1u || ti > 14u) return;
    int v[4]; unsigned o[4];
#pragma unroll
    for (int j = 0; j < 4; j++) { v[j] = tet[4 * f + j]; o[j] = g_occ[v[j]]; }
#pragma unroll
    for (int e = 0; e < 6; e++) {
        int p0 = c_be[2 * e], p1 = c_be[2 * e + 1];
        if (o[p0] != o[p1]) {
            int a = v[p0], b = v[p1];
            int amin = a < b ? a : b;
            int bmax = a < b ? b : a;
            unsigned p = g_boff[amin] + atomicAdd(&g_bfill[amin], 1u);
            unsigned slot = (unsigned)(6 * f + e);
            g_keys[p] = ((unsigned long long)(unsigned)bmax << 24) | (unsigned long long)slot;
        }
    }
}

// per-bucket insertion sort by (b, slot), then assign local unique ranks
__global__ void k_sort(int N) {
    int a = blockIdx.x * blockDim.x + threadIdx.x;
    if (a >= N) return;
    unsigned off = g_boff[a];
    unsigned L = g_bcnt[a];
    for (unsigned i = 1; i < L; i++) {
        unsigned long long key = g_keys[off + i];
        int j = (int)i - 1;
        while (j >= 0 && g_keys[off + j] > key) {
            g_keys[off + j + 1] = g_keys[off + j];
            j--;
        }
        g_keys[off + j + 1] = key;
    }
    unsigned u = 0;
    unsigned prevb = 0xFFFFFFFFu;
    for (unsigned i = 0; i < L; i++) {
        unsigned long long k = g_keys[off + i];
        unsigned b = (unsigned)(k >> 24);
        unsigned head = (b != prevb) ? 1u : 0u;
        if (head) { u++; prevb = b; }
        g_aux[off + i] = ((u - 1) << 1) | head;
    }
    g_ucnt[a] = u;
}

__global__ void k_efinal(int N) {
    int a = blockIdx.x * blockDim.x + threadIdx.x;
    if (a >= N) return;
    unsigned off = g_boff[a];
    unsigned L = g_bcnt[a];
    unsigned rb = g_urank[a];
    for (unsigned i = 0; i < L; i++) {
        unsigned long long k = g_keys[off + i];
        unsigned aux = g_aux[off + i];
        unsigned rank = rb + (aux >> 1);
        unsigned slot = (unsigned)(k & 0xFFFFFFull);
        g_idxmap[slot] = (int)rank;
        if (aux & 1u) {
            g_uea[rank] = a;
            g_ueb[rank] = (int)(unsigned)(k >> 24);
        }
    }
}

// edge interpolation -> verts (also first output section)
__global__ void k_interp(const float* __restrict__ pos, const float* __restrict__ sdf,
                         const float* __restrict__ thp, float* __restrict__ out) {
    unsigned r = blockIdx.x * blockDim.x + threadIdx.x;
    unsigned E = g_cnt[0];
    if (r >= E) return;
    int a = g_uea[r], b = g_ueb[r];
    float s0 = sdf[a], s1 = sdf[b];
    float th = *thp;
    if (s0 > 0.0f && s1 > 0.0f) { s0 -= th; s1 -= th; }
    float denom = s0 - s1;
    float w0 = -s1 / denom;
    float w1 = s0 / denom;
#pragma unroll
    for (int k = 0; k < 3; k++) {
        float val = pos[3 * a + k] * w0 + pos[3 * b + k] * w1;
        g_verts[3 * r + k] = val;
        out[3 * r + k] = val;
    }
}

__global__ void k_faces(int F, float* __restrict__ out) {
    int f = blockIdx.x * blockDim.x + threadIdx.x;
    if (f >= F) return;
    unsigned ti = g_ti[f];
    if (ti < 1u || ti > 14u) return;
    int nt = c_ntri[ti];
    unsigned E = g_cnt[0], NT1 = g_cnt[1];
    float* o = out + (size_t)3 * E;
    if (nt == 1) {
        unsigned base = 3u * g_sc[0 * MAXF + f];
#pragma unroll
        for (int j = 0; j < 3; j++)
            o[base + j] = (float)g_idxmap[6 * f + c_tri[ti][j]];
    } else {
        unsigned base = 3u * NT1 + 6u * g_sc[1 * MAXF + f];
#pragma unroll
        for (int j = 0; j < 6; j++)
            o[base + j] = (float)g_idxmap[6 * f + c_tri[ti][j]];
    }
}

__global__ void k_tets_build(const int* __restrict__ tet, int F, int N) {
    int f = blockIdx.x * blockDim.x + threadIdx.x;
    if (f >= F) return;
    unsigned ti = g_ti[f];
    unsigned T1 = g_cnt[3], T3 = g_cnt[4];
    if (ti == 15u) {
        unsigned row = T1 + 3u * T3 + g_sc[4 * MAXF + f];
#pragma unroll
        for (int j = 0; j < 4; j++)
            g_alltets[4 * row + j] = tet[4 * f + j];
    } else if (ti >= 1u && ti <= 14u) {
        int ntt = c_ntet[ti];
        if (ntt == 1) {
            unsigned row = g_sc[2 * MAXF + f];
#pragma unroll
            for (int j = 0; j < 4; j++) {
                int c = c_tet[ti][j];
                g_alltets[4 * row + j] = (c < 4) ? tet[4 * f + c] : N + g_idxmap[6 * f + (c - 4)];
            }
        } else {
            unsigned rowbase = T1 + 3u * g_sc[3 * MAXF + f];
#pragma unroll
            for (int j = 0; j < 12; j++) {
                int c = c_tet[ti][j];
                g_alltets[4 * rowbase + j] = (c < 4) ? tet[4 * f + c] : N + g_idxmap[6 * f + (c - 4)];
            }
        }
    }
}

__global__ void k_T() {
    g_cnt[8] = g_cnt[3] + 3u * g_cnt[4] + g_cnt[5];
}

__global__ void k_mark() {
    unsigned i = blockIdx.x * blockDim.x + threadIdx.x;
    unsigned n = 4u * g_cnt[8];
    if (i >= n) return;
    g_pres[g_alltets[i]] = 1u;
}

__global__ void k_vt(const float* __restrict__ pos, int N, int NV, float* __restrict__ out) {
    int v = blockIdx.x * blockDim.x + threadIdx.x;
    if (v >= NV) return;
    if (!g_pres[v]) return;
    unsigned r = g_rank2[v];
    unsigned E = g_cnt[0];
    unsigned Nf = g_cnt[1] + 2u * g_cnt[2];
    size_t ofs = (size_t)3 * E + (size_t)3 * Nf;
#pragma unroll
    for (int k = 0; k < 3; k++)
        out[ofs + 3 * (size_t)r + k] = (v < N) ? pos[3 * v + k] : g_verts[3 * (v - N) + k];
}

__global__ void k_tets_out(float* __restrict__ out) {
    unsigned i = blockIdx.x * blockDim.x + threadIdx.x;
    unsigned n = 4u * g_cnt[8];
    if (i >= n) return;
    unsigned E = g_cnt[0];
    unsigned Nf = g_cnt[1] + 2u * g_cnt[2];
    unsigned U = g_cnt[6];
    size_t ofs = (size_t)3 * E + (size_t)3 * Nf + (size_t)3 * U;
    out[ofs + i] = (float)g_rank2[g_alltets[i]];
}

// ---------------------------------------------------------------------------
// kernel_launch
// ---------------------------------------------------------------------------
extern "C" void kernel_launch(void* const* d_in, const int* in_sizes, int n_in,
                              void* d_out, int out_size) {
    const float* pos = (const float*)d_in[0];
    const float* sdf = (const float*)d_in[1];
    const int*   tet = (const int*)d_in[2];
    const float* th  = (const float*)d_in[3];
    float* out = (float*)d_out;

    int N = in_sizes[1];
    int F = in_sizes[2] / 4;
    int NV = N + 6 * F;     // value domain of tetmesh vertex ids

    // clear scratch used with atomics / presence
    k_clear_buckets<<<GRID(N), TPB>>>(N);
    k_clear_pres<<<GRID(NV), TPB>>>(NV);

    // occupancy + tet classification + crossing-edge bucket histogram
    k_occ<<<GRID(N), TPB>>>(sdf, th, N);
    k_ti<<<GRID(F), TPB>>>(tet, F);

    // exclusive scans of class flags (totals -> g_cnt)
    run_scan(0, 0, F, 1);   // NT1
    run_scan(1, 1, F, 2);   // NT2
    run_scan(2, 2, F, 3);   // T1
    run_scan(3, 3, F, 4);   // T3
    run_scan(4, 4, F, 5);   // INNER

    // edge buckets: offsets, scatter, per-bucket sort + unique ranking
    run_scan(5, 6, N, 7);   // bcnt -> boff
    k_scatter<<<GRID(F), TPB>>>(tet, F);
    k_sort<<<GRID(N), TPB>>>(N);
    run_scan(7, 8, N, 0);   // ucnt -> urank, total = E
    k_efinal<<<GRID(N), TPB>>>(N);

    // outputs section 1: interpolated verts
    k_interp<<<GRID(MAXSLOT), TPB>>>(pos, sdf, th, out);

    // outputs section 2: faces
    k_faces<<<GRID(F), TPB>>>(F, out);

    // tetmesh: build all_tets, unique via presence bitmap + scan
    k_tets_build<<<GRID(F), TPB>>>(tet, F, N);
    k_T<<<1, 1>>>();
    k_mark<<<GRID(4 * MAXT), TPB>>>();
    run_scan(9, 10, NV, 6); // presence -> rank2, total = U

    // outputs section 3: verts_tetmesh; section 4: tets_tetmesh indices
    k_vt<<<GRID(NV), TPB>>>(pos, N, NV, out);
    k_tets_out<<<GRID(4 * MAXT), TPB>>>(out);
}

// round 2
// speedup vs baseline: 1.5282x; 1.5282x over previous
#include <cuda_runtime.h>

#define MAXN 400000
#define MAXF 2000000
#define MAXSLOT (6 * MAXF)
#define MAXVAL (MAXN + MAXSLOT)
#define MAXT (3 * MAXF)
#define TPB 256
#define GRID(n) (((n) + TPB - 1) / TPB)

// ---------------------------------------------------------------------------
// Tables (device-global: divergent gathers go through L1, no c-bank replays)
// ---------------------------------------------------------------------------
__device__ const int d_tri[16][6] = {
    {-1,-1,-1,-1,-1,-1},{1,0,2,-1,-1,-1},{4,0,3,-1,-1,-1},{1,4,2,1,3,4},
    {3,1,5,-1,-1,-1},{2,3,0,2,5,3},{1,4,0,1,5,4},{4,2,5,-1,-1,-1},
    {4,5,2,-1,-1,-1},{4,1,0,4,5,1},{3,2,0,3,5,2},{1,3,5,-1,-1,-1},
    {4,1,2,4,3,1},{3,0,4,-1,-1,-1},{2,0,1,-1,-1,-1},{-1,-1,-1,-1,-1,-1}};
__device__ const int d_tet[16][12] = {
    {-1,-1,-1,-1,-1,-1,-1,-1,-1,-1,-1,-1},{0,4,5,6,-1,-1,-1,-1,-1,-1,-1,-1},
    {1,4,8,7,-1,-1,-1,-1,-1,-1,-1,-1},{7,1,8,6,5,1,7,6,5,0,1,6},
    {2,5,7,9,-1,-1,-1,-1,-1,-1,-1,-1},{4,0,6,7,9,0,7,6,7,0,9,2},
    {4,1,9,8,5,1,9,4,5,1,2,9},{6,0,1,2,8,6,1,2,9,6,8,2},
    {3,6,9,8,-1,-1,-1,-1,-1,-1,-1,-1},{5,0,4,8,5,0,8,3,5,8,9,3},
    {1,4,7,3,4,7,6,3,9,6,7,3},{0,1,5,3,5,1,9,3,5,1,7,9},
    {5,2,3,7,3,6,5,8,3,5,7,8},{0,4,7,8,0,3,8,7,0,3,7,2},
    {4,1,2,3,4,3,2,5,4,3,5,6},{0,1,2,3,-1,-1,-1,-1,-1,-1,-1,-1}};
__device__ const int d_be[12] = {0,1, 0,2, 0,3, 1,2, 1,3, 2,3};

// Bitmask class predicates (functions of ti only)
__device__ __forceinline__ unsigned f_valid(unsigned ti) { return (0x7FFEu >> ti) & 1u; }
__device__ __forceinline__ unsigned f_nt1(unsigned ti)   { return (0x6996u >> ti) & 1u; } // ti in {1,2,4,7,8,11,13,14}
__device__ __forceinline__ unsigned f_ntt1(unsigned ti)  { return (0x0116u >> ti) & 1u; } // ti in {1,2,4,8}

// packed 5-channel flag word: [0]=nt1 [12]=nt2 [24]=t1 [36]=t3 [48]=inner (12-bit fields)
__device__ __forceinline__ unsigned long long packflags(unsigned ti) {
    unsigned v  = f_valid(ti);
    unsigned n1 = v & f_nt1(ti);
    unsigned t1 = v & f_ntt1(ti);
    unsigned n2 = v ^ n1;
    unsigned t3 = v ^ t1;
    unsigned in = (ti == 15u) ? 1u : 0u;
    return (unsigned long long)n1
         | ((unsigned long long)n2 << 12)
         | ((unsigned long long)t1 << 24)
         | ((unsigned long long)t3 << 36)
         | ((unsigned long long)in << 48);
}

// ---------------------------------------------------------------------------
// Device scratch
// ---------------------------------------------------------------------------
__device__ unsigned char      g_occ[MAXN];
__device__ unsigned char      g_ti[MAXF];
__device__ unsigned long long g_off[MAXF];      // per-tet packed (tet_off<<32 | tri_off)
__device__ unsigned           g_bcnt[MAXN];
__device__ unsigned           g_boff[MAXN];
__device__ unsigned           g_bfill[MAXN];
__device__ unsigned           g_ucnt[MAXN];
__device__ unsigned           g_urank[MAXN];
__device__ unsigned long long g_keys[MAXSLOT];
__device__ unsigned           g_aux[MAXSLOT];
__device__ int                g_idxmap[MAXSLOT];
__device__ int                g_uea[MAXSLOT];
__device__ int                g_ueb[MAXSLOT];
__device__ float              g_verts[3 * MAXSLOT];
__device__ int4               g_alltets[MAXT];
__device__ uint4              g_pres4[(MAXVAL + 15) / 16];   // byte presence, 16B aligned
__device__ unsigned           g_rank2[MAXVAL];
__device__ unsigned           g_partf[5 * 1024];             // flag-scan partials
__device__ unsigned           g_part2[4096];                 // generic scan partials
__device__ unsigned           g_cnt[16];
// g_cnt: [0]=E [1]=NT1 [2]=NT2 [3]=T1 [4]=T3 [5]=INNER [6]=U [8]=T [9]=N+E

// ---------------------------------------------------------------------------
// Fused 5-channel flag scan over g_ti (3 launches total)
// ---------------------------------------------------------------------------
__global__ void fs_k1(int F) {
    __shared__ unsigned long long sh[TPB];
    int t = threadIdx.x;
    int base = blockIdx.x * (TPB * 8) + t * 8;
    unsigned long long p = 0;
#pragma unroll
    for (int i = 0; i < 8; i++) {
        int f = base + i;
        if (f < F) p += packflags(g_ti[f]);
    }
    sh[t] = p; __syncthreads();
    for (int d = TPB / 2; d > 0; d >>= 1) {
        if (t < d) sh[t] += sh[t + d];
        __syncthreads();
    }
    if (t == 0) {
        unsigned long long s = sh[0];
        g_partf[0 * 1024 + blockIdx.x] = (unsigned)(s & 0xFFF);
        g_partf[1 * 1024 + blockIdx.x] = (unsigned)((s >> 12) & 0xFFF);
        g_partf[2 * 1024 + blockIdx.x] = (unsigned)((s >> 24) & 0xFFF);
        g_partf[3 * 1024 + blockIdx.x] = (unsigned)((s >> 36) & 0xFFF);
        g_partf[4 * 1024 + blockIdx.x] = (unsigned)((s >> 48) & 0xFFF);
    }
}

__global__ void fs_k2(int nb) {
    __shared__ unsigned sh[1024];
    int t = threadIdx.x;
    for (int c = 0; c < 5; c++) {
        unsigned x = (t < nb) ? g_partf[c * 1024 + t] : 0u;
        sh[t] = x; __syncthreads();
        for (int d = 1; d < 1024; d <<= 1) {
            unsigned y = 0;
            if (t >= d) y = sh[t - d];
            __syncthreads();
            if (t >= d) sh[t] += y;
            __syncthreads();
        }
        if (t < nb) g_partf[c * 1024 + t] = sh[t] - x;   // exclusive
        if (t == 0) g_cnt[1 + c] = sh[1023];
        __syncthreads();
    }
}

__global__ void fs_k3(int F) {
    __shared__ unsigned long long sh[TPB];
    int t = threadIdx.x, b = blockIdx.x;
    int base = b * (TPB * 8) + t * 8;
    unsigned lti[8];
    unsigned long long p = 0;
#pragma unroll
    for (int i = 0; i < 8; i++) {
        int f = base + i;
        lti[i] = (f < F) ? (unsigned)g_ti[f] : 0u;
        p += packflags(lti[i]);
    }
    sh[t] = p; __syncthreads();
    for (int d = 1; d < TPB; d <<= 1) {
        unsigned long long y = 0;
        if (t >= d) y = sh[t - d];
        __syncthreads();
        if (t >= d) sh[t] += y;
        __syncthreads();
    }
    unsigned long long run = (t > 0) ? sh[t - 1] : 0ull;
    unsigned b0 = g_partf[0 * 1024 + b], b1 = g_partf[1 * 1024 + b];
    unsigned b2 = g_partf[2 * 1024 + b], b3 = g_partf[3 * 1024 + b];
    unsigned b4 = g_partf[4 * 1024 + b];
#pragma unroll
    for (int i = 0; i < 8; i++) {
        int f = base + i;
        if (f >= F) break;
        unsigned ti = lti[i];
        unsigned trioff = 0, tetoff = 0;
        if (f_valid(ti)) {
            trioff = f_nt1(ti)  ? b0 + (unsigned)(run & 0xFFF)
                                : b1 + (unsigned)((run >> 12) & 0xFFF);
            tetoff = f_ntt1(ti) ? b2 + (unsigned)((run >> 24) & 0xFFF)
                                : b3 + (unsigned)((run >> 36) & 0xFFF);
        } else if (ti == 15u) {
            tetoff = b4 + (unsigned)((run >> 48) & 0xFFF);
        }
        g_off[f] = ((unsigned long long)tetoff << 32) | trioff;
        run += packflags(ti);
    }
}

// ---------------------------------------------------------------------------
// Generic u32 exclusive scan over small N arrays (bcnt->boff, ucnt->urank)
// ---------------------------------------------------------------------------
__device__ __forceinline__ unsigned* selarr(int s) {
    switch (s) {
        case 0: return g_bcnt;
        case 1: return g_boff;
        case 2: return g_ucnt;
        default: return g_urank;
    }
}

__global__ void s_k1(int insel, int outsel, int n) {
    __shared__ unsigned sh[TPB];
    const unsigned* in = selarr(insel);
    unsigned* out = selarr(outsel);
    int t = threadIdx.x;
    int base = blockIdx.x * (TPB * 8) + t * 8;
    unsigned v[8]; unsigned s = 0;
#pragma unroll
    for (int i = 0; i < 8; i++) {
        unsigned x = (base + i < n) ? in[base + i] : 0u;
        v[i] = s; s += x;
    }
    sh[t] = s; __syncthreads();
    for (int d = 1; d < TPB; d <<= 1) {
        unsigned y = 0;
        if (t >= d) y = sh[t - d];
        __syncthreads();
        if (t >= d) sh[t] += y;
        __syncthreads();
    }
    unsigned off = (t > 0) ? sh[t - 1] : 0u;
    if (t == 0) g_part2[blockIdx.x] = sh[TPB - 1];
    __syncthreads();
#pragma unroll
    for (int i = 0; i < 8; i++)
        if (base + i < n) out[base + i] = v[i] + off;
}

__global__ void s_k2(int nb, int counterIdx) {
    __shared__ unsigned sh[1024];
    __shared__ unsigned carry_s;
    int t = threadIdx.x;
    if (t == 0) carry_s = 0;
    __syncthreads();
    for (int base = 0; base < nb; base += 1024) {
        int i = base + t;
        unsigned x = (i < nb) ? g_part2[i] : 0u;
        sh[t] = x; __syncthreads();
        for (int d = 1; d < 1024; d <<= 1) {
            unsigned y = 0;
            if (t >= d) y = sh[t - d];
            __syncthreads();
            if (t >= d) sh[t] += y;
            __syncthreads();
        }
        unsigned c = carry_s;
        unsigned excl = c + ((t > 0) ? sh[t - 1] : 0u);
        unsigned tot = sh[1023];
        __syncthreads();
        if (i < nb) g_part2[i] = excl;
        if (t == 0) carry_s = c + tot;
        __syncthreads();
    }
    if (t == 0 && counterIdx >= 0) g_cnt[counterIdx] = carry_s;
}

__global__ void s_k3(int outsel, int n) {
    unsigned* out = selarr(outsel);
    unsigned add = g_part2[blockIdx.x];
    int base = blockIdx.x * (TPB * 8) + threadIdx.x * 8;
#pragma unroll
    for (int i = 0; i < 8; i++)
        if (base + i < n) out[base + i] += add;
}

static void run_scan(int insel, int outsel, int n, int counterIdx) {
    int nb = (n + TPB * 8 - 1) / (TPB * 8);
    s_k1<<<nb, TPB>>>(insel, outsel, n);
    s_k2<<<1, 1024>>>(nb, counterIdx);
    s_k3<<<nb, TPB>>>(outsel, n);
}

// ---------------------------------------------------------------------------
// Pipeline kernels
// ---------------------------------------------------------------------------
__global__ void k_clear_buckets(int n) {
    int i = blockIdx.x * blockDim.x + threadIdx.x;
    if (i < n) { g_bcnt[i] = 0; g_bfill[i] = 0; }
}

__global__ void k_occ(const float* __restrict__ sdf, const float* __restrict__ th, int N) {
    int i = blockIdx.x * blockDim.x + threadIdx.x;
    if (i >= N) return;
    float t = *th;
    float s = sdf[i];
    g_occ[i] = (s > 0.0f && s <= t) ? 1 : 0;
}

__global__ void k_ti(const int4* __restrict__ tet, int F) {
    int f = blockIdx.x * blockDim.x + threadIdx.x;
    if (f >= F) return;
    int4 q = tet[f];
    int v[4] = {q.x, q.y, q.z, q.w};
    unsigned o[4];
#pragma unroll
    for (int j = 0; j < 4; j++) o[j] = g_occ[v[j]];
    unsigned ti = o[0] | (o[1] << 1) | (o[2] << 2) | (o[3] << 3);
    g_ti[f] = (unsigned char)ti;
    if (f_valid(ti)) {
#pragma unroll
        for (int e = 0; e < 6; e++) {
            int p0 = d_be[2 * e], p1 = d_be[2 * e + 1];
            if (o[p0] != o[p1]) {
                int a = v[p0], b = v[p1];
                int amin = a < b ? a : b;
                atomicAdd(&g_bcnt[amin], 1u);
            }
        }
    }
}

__global__ void k_scatter(const int4* __restrict__ tet, int F) {
    int f = blockIdx.x * blockDim.x + threadIdx.x;
    if (f >= F) return;
    unsigned ti = g_ti[f];
    if (!f_valid(ti)) return;
    int4 q = tet[f];
    int v[4] = {q.x, q.y, q.z, q.w};
#pragma unroll
    for (int e = 0; e < 6; e++) {
        int p0 = d_be[2 * e], p1 = d_be[2 * e + 1];
        if (((ti >> p0) ^ (ti >> p1)) & 1u) {
            int a = v[p0], b = v[p1];
            int amin = a < b ? a : b;
            int bmax = a < b ? b : a;
            unsigned p = g_boff[amin] + atomicAdd(&g_bfill[amin], 1u);
            unsigned slot = (unsigned)(6 * f + e);
            g_keys[p] = ((unsigned long long)(unsigned)bmax << 24) | (unsigned long long)slot;
        }
    }
}

__global__ void k_sort(int N) {
    int a = blockIdx.x * blockDim.x + threadIdx.x;
    if (a >= N) return;
    unsigned off = g_boff[a];
    unsigned L = g_bcnt[a];
    for (unsigned i = 1; i < L; i++) {
        unsigned long long key = g_keys[off + i];
        int j = (int)i - 1;
        while (j >= 0 && g_keys[off + j] > key) {
            g_keys[off + j + 1] = g_keys[off + j];
            j--;
        }
        g_keys[off + j + 1] = key;
    }
    unsigned u = 0;
    unsigned prevb = 0xFFFFFFFFu;
    for (unsigned i = 0; i < L; i++) {
        unsigned long long k = g_keys[off + i];
        unsigned b = (unsigned)(k >> 24);
        unsigned head = (b != prevb) ? 1u : 0u;
        if (head) { u++; prevb = b; }
        g_aux[off + i] = ((u - 1) << 1) | head;
    }
    g_ucnt[a] = u;
}

__global__ void k_efinal(int N) {
    int a = blockIdx.x * blockDim.x + threadIdx.x;
    if (a >= N) return;
    unsigned off = g_boff[a];
    unsigned L = g_bcnt[a];
    unsigned rb = g_urank[a];
    for (unsigned i = 0; i < L; i++) {
        unsigned long long k = g_keys[off + i];
        unsigned aux = g_aux[off + i];
        unsigned rank = rb + (aux >> 1);
        unsigned slot = (unsigned)(k & 0xFFFFFFull);
        g_idxmap[slot] = (int)rank;
        if (aux & 1u) {
            g_uea[rank] = a;
            g_ueb[rank] = (int)(unsigned)(k >> 24);
        }
    }
}

__global__ void k_T(int N) {
    g_cnt[8] = g_cnt[3] + 3u * g_cnt[4] + g_cnt[5];
    g_cnt[9] = (unsigned)N + g_cnt[0];
}

__global__ void k_interp(const float* __restrict__ pos, const float* __restrict__ sdf,
                         const float* __restrict__ thp, float* __restrict__ out) {
    unsigned E = g_cnt[0];
    unsigned base = blockIdx.x * (TPB * 4u) + threadIdx.x;
    if (base >= E) return;   // whole tail blocks exit (strided layout keeps first lane earliest)
    float th = *thp;
#pragma unroll
    for (int k4 = 0; k4 < 4; k4++) {
        unsigned r = base + k4 * TPB;
        if (r >= E) break;
        int a = g_uea[r], b = g_ueb[r];
        float s0 = sdf[a], s1 = sdf[b];
        if (s0 > 0.0f && s1 > 0.0f) { s0 -= th; s1 -= th; }
        float denom = s0 - s1;
        float w0 = -s1 / denom;
        float w1 = s0 / denom;
#pragma unroll
        for (int k = 0; k < 3; k++) {
            float val = pos[3 * a + k] * w0 + pos[3 * b + k] * w1;
            g_verts[3 * r + k] = val;
            out[3 * r + k] = val;
        }
    }
}

__global__ void k_faces(int F, float* __restrict__ out) {
    int f = blockIdx.x * blockDim.x + threadIdx.x;
    if (f >= F) return;
    unsigned ti = g_ti[f];
    if (!f_valid(ti)) return;
    unsigned lo = (unsigned)g_off[f];
    unsigned E = g_cnt[0], NT1 = g_cnt[1];
    float* o = out + (size_t)3 * E;
    if (f_nt1(ti)) {
        unsigned base = 3u * lo;
#pragma unroll
        for (int j = 0; j < 3; j++)
            o[base + j] = (float)g_idxmap[6 * f + d_tri[ti][j]];
    } else {
        unsigned base = 3u * NT1 + 6u * lo;
#pragma unroll
        for (int j = 0; j < 6; j++)
            o[base + j] = (float)g_idxmap[6 * f + d_tri[ti][j]];
    }
}

__global__ void k_tets_build(const int4* __restrict__ tet, int F, int N) {
    int f = blockIdx.x * blockDim.x + threadIdx.x;
    if (f >= F) return;
    unsigned ti = g_ti[f];
    unsigned hi = (unsigned)(g_off[f] >> 32);
    unsigned T1 = g_cnt[3], T3 = g_cnt[4];
    if (ti == 15u) {
        g_alltets[T1 + 3u * T3 + hi] = tet[f];
    } else if (f_valid(ti)) {
        int4 q = tet[f];
        int v[4] = {q.x, q.y, q.z, q.w};
        if (f_ntt1(ti)) {
            int r[4];
#pragma unroll
            for (int j = 0; j < 4; j++) {
                int c = d_tet[ti][j];
                r[j] = (c < 4) ? v[c] : N + g_idxmap[6 * f + (c - 4)];
            }
            g_alltets[hi] = make_int4(r[0], r[1], r[2], r[3]);
        } else {
            unsigned rowbase = T1 + 3u * hi;
#pragma unroll
            for (int t3i = 0; t3i < 3; t3i++) {
                int r[4];
#pragma unroll
                for (int j = 0; j < 4; j++) {
                    int c = d_tet[ti][4 * t3i + j];
                    r[j] = (c < 4) ? v[c] : N + g_idxmap[6 * f + (c - 4)];
                }
                g_alltets[rowbase + t3i] = make_int4(r[0], r[1], r[2], r[3]);
            }
        }
    }
}

__global__ void k_clear_pres() {
    unsigned n = g_cnt[9];                       // bytes
    unsigned nw = (n + 15u) / 16u;               // uint4 words
    unsigned i = blockIdx.x * blockDim.x + threadIdx.x;
    if (i >= nw) return;
    g_pres4[i] = make_uint4(0u, 0u, 0u, 0u);
}

__global__ void k_mark() {
    unsigned T = g_cnt[8];
    unsigned base = blockIdx.x * (TPB * 4u) + threadIdx.x;
    if (base >= T) return;
    unsigned char* pres = (unsigned char*)g_pres4;
#pragma unroll
    for (int k4 = 0; k4 < 4; k4++) {
        unsigned i = base + k4 * TPB;
        if (i >= T) break;
        int4 q = g_alltets[i];
        pres[q.x] = 1; pres[q.y] = 1; pres[q.z] = 1; pres[q.w] = 1;
    }
}

// presence byte scan: k1 static over full MAXVAL (beyond-n bytes always zero)
__global__ void ps_k1() {
    __shared__ unsigned sh[TPB];
    const unsigned* w = (const unsigned*)g_pres4;
    const unsigned NW = (MAXVAL + 3) / 4;
    int t = threadIdx.x;
    unsigned base = blockIdx.x * (TPB * 4u) + t * 4u;
    unsigned s = 0;
#pragma unroll
    for (int i = 0; i < 4; i++) {
        unsigned idx = base + i;
        if (idx < NW) s += (w[idx] * 0x01010101u) >> 24;
    }
    sh[t] = s; __syncthreads();
    for (int d = TPB / 2; d > 0; d >>= 1) {
        if (t < d) sh[t] += sh[t + d];
        __syncthreads();
    }
    if (t == 0) g_part2[blockIdx.x] = sh[0];
}

__global__ void ps_k2(int nb) {
    __shared__ unsigned sh[1024];
    __shared__ unsigned carry_s;
    int t = threadIdx.x;
    if (t == 0) carry_s = 0;
    __syncthreads();
    for (int base = 0; base < nb; base += 1024) {
        int i = base + t;
        unsigned x = (i < nb) ? g_part2[i] : 0u;
        sh[t] = x; __syncthreads();
        for (int d = 1; d < 1024; d <<= 1) {
            unsigned y = 0;
            if (t >= d) y = sh[t - d];
            __syncthreads();
            if (t >= d) sh[t] += y;
            __syncthreads();
        }
        unsigned c = carry_s;
        unsigned excl = c + ((t > 0) ? sh[t - 1] : 0u);
        unsigned tot = sh[1023];
        __syncthreads();
        if (i < nb) g_part2[i] = excl;
        if (t == 0) carry_s = c + tot;
        __syncthreads();
    }
    if (t == 0) g_cnt[6] = carry_s;
}

// write rank2 only at present positions (dyn length)
__global__ void ps_k3() {
    __shared__ unsigned sh[TPB];
    unsigned n = g_cnt[9];
    int t = threadIdx.x;
    unsigned blockByteBase = blockIdx.x * (TPB * 16u);
    if (blockByteBase >= n) return;
    const unsigned* w = (const unsigned*)g_pres4;
    const unsigned NW = (MAXVAL + 3) / 4;
    unsigned base = blockIdx.x * (TPB * 4u) + t * 4u;
    unsigned wv[4]; unsigned s = 0;
#pragma unroll
    for (int i = 0; i < 4; i++) {
        unsigned idx = base + i;
        wv[i] = (idx < NW) ? w[idx] : 0u;
        s += (wv[i] * 0x01010101u) >> 24;
    }
    sh[t] = s; __syncthreads();
    for (int d = 1; d < TPB; d <<= 1) {
        unsigned y = 0;
        if (t >= d) y = sh[t - d];
        __syncthreads();
        if (t >= d) sh[t] += y;
        __syncthreads();
    }
    unsigned run = g_part2[blockIdx.x] + ((t > 0) ? sh[t - 1] : 0u);
#pragma unroll
    for (int i = 0; i < 4; i++) {
        unsigned v = wv[i];
        unsigned byteBase = (base + i) * 4u;
#pragma unroll
        for (int bt = 0; bt < 4; bt++) {
            if ((v >> (8 * bt)) & 1u) {
                g_rank2[byteBase + bt] = run;
                run++;
            }
        }
    }
}

__global__ void k_vt(const float* __restrict__ pos, int N, float* __restrict__ out) {
    unsigned n = g_cnt[9];
    unsigned base = blockIdx.x * (TPB * 4u) + threadIdx.x;
    if (base >= n) return;
    const unsigned char* pres = (const unsigned char*)g_pres4;
    unsigned E = g_cnt[0];
    unsigned Nf = g_cnt[1] + 2u * g_cnt[2];
    size_t ofs = (size_t)3 * E + (size_t)3 * Nf;
#pragma unroll
    for (int k4 = 0; k4 < 4; k4++) {
        unsigned v = base + k4 * TPB;
        if (v >= n) break;
        if (!pres[v]) continue;
        unsigned r = g_rank2[v];
#pragma unroll
        for (int k = 0; k < 3; k++)
            out[ofs + 3 * (size_t)r + k] =
                (v < (unsigned)N) ? pos[3 * v + k] : g_verts[3 * (v - N) + k];
    }
}

__global__ void k_tets_out(float* __restrict__ out) {
    unsigned T = g_cnt[8];
    unsigned base = blockIdx.x * (TPB * 4u) + threadIdx.x;
    if (base >= T) return;
    unsigned E = g_cnt[0];
    unsigned Nf = g_cnt[1] + 2u * g_cnt[2];
    unsigned U = g_cnt[6];
    size_t ofs = (size_t)3 * E + (size_t)3 * Nf + (size_t)3 * U;
#pragma unroll
    for (int k4 = 0; k4 < 4; k4++) {
        unsigned i = base + k4 * TPB;
        if (i >= T) break;
        int4 q = g_alltets[i];
        out[ofs + 4 * (size_t)i + 0] = (float)g_rank2[q.x];
        out[ofs + 4 * (size_t)i + 1] = (float)g_rank2[q.y];
        out[ofs + 4 * (size_t)i + 2] = (float)g_rank2[q.z];
        out[ofs + 4 * (size_t)i + 3] = (float)g_rank2[q.w];
    }
}

// ---------------------------------------------------------------------------
// kernel_launch
// ---------------------------------------------------------------------------
extern "C" void kernel_launch(void* const* d_in, const int* in_sizes, int n_in,
                              void* d_out, int out_size) {
    const float* pos = (const float*)d_in[0];
    const float* sdf = (const float*)d_in[1];
    const int4*  tet = (const int4*)d_in[2];
    const float* th  = (const float*)d_in[3];
    float* out = (float*)d_out;

    int N = in_sizes[1];
    int F = in_sizes[2] / 4;

    k_clear_buckets<<<GRID(N), TPB>>>(N);
    k_occ<<<GRID(N), TPB>>>(sdf, th, N);
    k_ti<<<GRID(F), TPB>>>(tet, F);

    // fused 5-channel flag scan over g_ti
    int nbf = (F + TPB * 8 - 1) / (TPB * 8);
    fs_k1<<<nbf, TPB>>>(F);
    fs_k2<<<1, 1024>>>(nbf);
    fs_k3<<<nbf, TPB>>>(F);

    // edge buckets
    run_scan(0, 1, N, -1);                 // bcnt -> boff
    k_scatter<<<GRID(F), TPB>>>(tet, F);
    k_sort<<<GRID(N), TPB>>>(N);
    run_scan(2, 3, N, 0);                  // ucnt -> urank, total = E
    k_efinal<<<GRID(N), TPB>>>(N);

    k_T<<<1, 1>>>(N);                       // T and N+E

    // outputs: interpolated verts + faces
    k_interp<<<GRID(MAXSLOT / 4), TPB>>>(pos, sdf, th, out);
    k_faces<<<GRID(F), TPB>>>(F, out);

    // tetmesh unique via byte presence over dynamic domain [0, N+E)
    k_tets_build<<<GRID(F), TPB>>>(tet, F, N);
    k_clear_pres<<<GRID(MAXVAL / 16 + 1), TPB>>>();
    k_mark<<<GRID(MAXT / 4), TPB>>>();
    int nbp = ((MAXVAL + 3) / 4 + TPB * 4 - 1) / (TPB * 4);
    ps_k1<<<nbp, TPB>>>();
    ps_k2<<<1, 1024>>>(nbp);
    ps_k3<<<nbp, TPB>>>();

    k_vt<<<GRID(MAXVAL / 4 + 1), TPB>>>(pos, N, out);
    k_tets_out<<<GRID(MAXT / 4), TPB>>>(out);
}